// round 3
// baseline (speedup 1.0000x reference)
#include <cuda_runtime.h>

// Problem constants
#define BATCH   64
#define TSTEPS  512
#define IN_DIM  1024
#define HID     1024
#define MTOT    (BATCH * TSTEPS)           // 32768 rows of the GEMM

// ALPHA = exp(-1/20) rounded to fp32
#define ALPHA_F 0.95122942450071400909f

// Scratch for the synaptic currents I[b,t,h] (128 MiB).
__device__ float g_I[(size_t)MTOT * HID];

// Packed dual-FMA: d.lo = rn(a.lo*b.lo + c.lo), d.hi = rn(a.hi*b.hi + c.hi)
// Bitwise identical to two scalar fmaf's. SASS: FFMA2 (sm_10x only).
__device__ __forceinline__ unsigned long long fma2(unsigned long long a,
                                                   unsigned long long b,
                                                   unsigned long long c)
{
    unsigned long long d;
    asm("fma.rn.f32x2 %0, %1, %2, %3;" : "=l"(d) : "l"(a), "l"(b), "l"(c));
    return d;
}

__device__ __forceinline__ unsigned long long bcast2(float x)
{
    unsigned int xi = __float_as_uint(x);
    unsigned long long d;
    asm("mov.b64 %0, {%1, %1};" : "=l"(d) : "r"(xi));
    return d;
}

// ---------------------------------------------------------------------------
// GEMM: g_I[m, n] = sum_k x[m, k] * W[n, k]  + b[n]
// Strictly in-order ascending-k accumulation per output, FMA each step
// (bit-exact vs reference). Packed f32x2: two outputs (adjacent n) per
// instruction — per-lane rounding order identical to scalar version.
// 128x128 tile, BK=16, 256 threads, 4x16 per-thread microtile.
// ---------------------------------------------------------------------------
#define BM 128
#define BN 128
#define BK 16

__global__ __launch_bounds__(256, 2)
void snn_gemm_kernel(const float* __restrict__ A,      // x  [MTOT, IN_DIM]
                     const float* __restrict__ Wt,     // W  [HID, IN_DIM]
                     const float* __restrict__ bias)   // b  [HID]
{
    __shared__ float As[BK][BM];   // As[k][m]
    __shared__ float Bs[BK][BN];   // Bs[k][n]

    const int tid  = threadIdx.x;          // 0..255
    const int tx   = tid & 7;              // col group: 16 cols each
    const int ty   = tid >> 3;             // row group: 4 rows each (0..31)
    const int row0 = blockIdx.y * BM;
    const int col0 = blockIdx.x * BN;

    // acc pairs over adjacent n: acc2[i][j] holds (n=2j, n=2j+1) for row i
    unsigned long long acc2[4][8];
#pragma unroll
    for (int i = 0; i < 4; i++)
#pragma unroll
        for (int j = 0; j < 8; j++) acc2[i][j] = 0ull;

    for (int k0 = 0; k0 < IN_DIM; k0 += BK) {
        // Cooperative loads: each tile is 128x16 fp32 = 512 float4.
#pragma unroll
        for (int i = 0; i < 2; i++) {
            const int f = tid + i * 256;       // 0..511
            const int r = f >> 2;              // row within tile
            const int c = (f & 3) * 4;         // k offset within tile

            float4 av = *reinterpret_cast<const float4*>(
                A + (size_t)(row0 + r) * IN_DIM + k0 + c);
            As[c + 0][r] = av.x;
            As[c + 1][r] = av.y;
            As[c + 2][r] = av.z;
            As[c + 3][r] = av.w;

            float4 wv = *reinterpret_cast<const float4*>(
                Wt + (size_t)(col0 + r) * IN_DIM + k0 + c);
            Bs[c + 0][r] = wv.x;
            Bs[c + 1][r] = wv.y;
            Bs[c + 2][r] = wv.z;
            Bs[c + 3][r] = wv.w;
        }
        __syncthreads();

#pragma unroll
        for (int kk = 0; kk < BK; kk++) {
            // a: 4 rows, broadcast each into both halves of a pair
            float a[4];
            *reinterpret_cast<float4*>(a) =
                *reinterpret_cast<const float4*>(&As[kk][ty * 4]);
            unsigned long long aa[4];
#pragma unroll
            for (int i = 0; i < 4; i++) aa[i] = bcast2(a[i]);

            // b: 16 cols = 8 lane pairs, already adjacent in shared
            unsigned long long bb[8];
            ulonglong2 t0 = *reinterpret_cast<const ulonglong2*>(&Bs[kk][tx * 16 + 0]);
            ulonglong2 t1 = *reinterpret_cast<const ulonglong2*>(&Bs[kk][tx * 16 + 4]);
            ulonglong2 t2 = *reinterpret_cast<const ulonglong2*>(&Bs[kk][tx * 16 + 8]);
            ulonglong2 t3 = *reinterpret_cast<const ulonglong2*>(&Bs[kk][tx * 16 + 12]);
            bb[0] = t0.x; bb[1] = t0.y; bb[2] = t1.x; bb[3] = t1.y;
            bb[4] = t2.x; bb[5] = t2.y; bb[6] = t3.x; bb[7] = t3.y;

#pragma unroll
            for (int i = 0; i < 4; i++)
#pragma unroll
                for (int j = 0; j < 8; j++)
                    acc2[i][j] = fma2(aa[i], bb[j], acc2[i][j]);
        }
        __syncthreads();
    }

    // Bias: single rounded add after the full K sum (matches "einsum + b").
#pragma unroll
    for (int i = 0; i < 4; i++) {
        const int r = row0 + ty * 4 + i;
#pragma unroll
        for (int j = 0; j < 8; j += 2) {
            const int c = col0 + tx * 16 + j * 2;
            float2 p0 = *reinterpret_cast<float2*>(&acc2[i][j + 0]);
            float2 p1 = *reinterpret_cast<float2*>(&acc2[i][j + 1]);
            float4 o;
            o.x = __fadd_rn(p0.x, bias[c + 0]);
            o.y = __fadd_rn(p0.y, bias[c + 1]);
            o.z = __fadd_rn(p1.x, bias[c + 2]);
            o.w = __fadd_rn(p1.y, bias[c + 3]);
            *reinterpret_cast<float4*>(&g_I[(size_t)r * HID + c]) = o;
        }
    }
}

// ---------------------------------------------------------------------------
// LIF scan: one thread per (b, h) neuron, sequential over t.
// mem = fma.rn(alpha, mem, I); spike = (mem >= 1); hard reset.
// Unroll 8 with batched loads for MLP=8; streaming loads (read-once data).
// ---------------------------------------------------------------------------
__global__ __launch_bounds__(128)
void snn_scan_kernel(float* __restrict__ spikes,     // [B, T, H]
                     float* __restrict__ mem_final)  // [B, H]
{
    const int idx = blockIdx.x * blockDim.x + threadIdx.x;   // 0..65535
    const int b = idx >> 10;          // / HID
    const int h = idx & (HID - 1);

    const float* ip = g_I + (size_t)b * TSTEPS * HID + h;
    float* sp = spikes + (size_t)b * TSTEPS * HID + h;

    float mem = 0.0f;
    for (int t0 = 0; t0 < TSTEPS; t0 += 8) {
        float cur[8];
#pragma unroll
        for (int u = 0; u < 8; u++)
            cur[u] = __ldcg(ip + (size_t)(t0 + u) * HID);

        float sv[8];
#pragma unroll
        for (int u = 0; u < 8; u++) {
            mem = fmaf(ALPHA_F, mem, cur[u]);    // fused: one rounding
            const bool fire = (mem >= 1.0f);
            sv[u] = fire ? 1.0f : 0.0f;
            if (fire) mem = 0.0f;
        }
#pragma unroll
        for (int u = 0; u < 8; u++)
            sp[(size_t)(t0 + u) * HID] = sv[u];
    }
    mem_final[idx] = mem;
}

// ---------------------------------------------------------------------------
// Launch
// ---------------------------------------------------------------------------
extern "C" void kernel_launch(void* const* d_in, const int* in_sizes, int n_in,
                              void* d_out, int out_size)
{
    const float* x = (const float*)d_in[0];   // [B, T, IN_DIM]
    const float* W = (const float*)d_in[1];   // [HID, IN_DIM]
    const float* b = (const float*)d_in[2];   // [HID]

    float* out        = (float*)d_out;
    float* spikes     = out;                                  // [B, T, H]
    float* mem_final  = out + (size_t)BATCH * TSTEPS * HID;   // [B, H]

    dim3 ggrid(HID / BN, MTOT / BM);    // (8, 256)
    snn_gemm_kernel<<<ggrid, 256>>>(x, W, b);

    snn_scan_kernel<<<(BATCH * HID) / 128, 128>>>(spikes, mem_final);
}